// round 5
// baseline (speedup 1.0000x reference)
#include <cuda_runtime.h>
#include <cuda_bf16.h>
#include <cstdint>

// Problem constants
#define VOCAB   50000
#define DDIM    128
#define CCH     128
#define NCLS    200
#define NSEQ    4096
#define SLEN    128
#define NVID    256

// Derived
#define XROWS   132            // 128 tokens + 4 zero-pad rows (for j up to 4)
#define XPITCH  136            // bf16 elements per row (272B -> conflict-free ldmatrix)
#define BPITCH  136
#define NSLOT   12             // 3 (k=3) + 4 (k=4) + 5 (k=5) weight slices of [128][128]

// Scratch in device globals (no allocations allowed)
__device__ __nv_bfloat16 g_emb[(size_t)VOCAB * DDIM];          // 12.8 MB
__device__ __nv_bfloat16 g_wcat[NSLOT * DDIM * CCH];           // 393 KB

// ---------------------------------------------------------------------------
// Conversion / init kernels
// ---------------------------------------------------------------------------
__global__ void cvt_emb_kernel(const float* __restrict__ emb) {
    int64_t i = (int64_t)blockIdx.x * blockDim.x + threadIdx.x;
    int64_t n = (int64_t)VOCAB * DDIM;
    if (i < n) g_emb[i] = __float2bfloat16(emb[i]);
}

__global__ void cvt_w_kernel(const float* __restrict__ W3,
                             const float* __restrict__ W4,
                             const float* __restrict__ W5) {
    int i = blockIdx.x * blockDim.x + threadIdx.x;  // total 196608
    const int n3 = 3 * DDIM * CCH;       // 49152
    const int n4 = n3 + 4 * DDIM * CCH;  // 114688
    const int n5 = n4 + 5 * DDIM * CCH;  // 196608
    if (i < n3)       g_wcat[i] = __float2bfloat16(W3[i]);
    else if (i < n4)  g_wcat[i] = __float2bfloat16(W4[i - n3]);
    else if (i < n5)  g_wcat[i] = __float2bfloat16(W5[i - n4]);
}

__global__ void zero_out_kernel(float* __restrict__ out) {
    int i = blockIdx.x * blockDim.x + threadIdx.x;
    if (i < NVID * NCLS) out[i] = 0.0f;   // sigmoid scores are > 0, so 0 is a safe -inf
}

// ---------------------------------------------------------------------------
// MMA / async-copy helpers
// ---------------------------------------------------------------------------
__device__ __forceinline__ void ldsm_x4(uint32_t* r, uint32_t addr) {
    asm volatile("ldmatrix.sync.aligned.m8n8.x4.shared.b16 {%0,%1,%2,%3}, [%4];\n"
                 : "=r"(r[0]), "=r"(r[1]), "=r"(r[2]), "=r"(r[3]) : "r"(addr));
}
__device__ __forceinline__ void ldsm_x4_t(uint32_t* r, uint32_t addr) {
    asm volatile("ldmatrix.sync.aligned.m8n8.x4.trans.shared.b16 {%0,%1,%2,%3}, [%4];\n"
                 : "=r"(r[0]), "=r"(r[1]), "=r"(r[2]), "=r"(r[3]) : "r"(addr));
}
__device__ __forceinline__ void mma_bf16(float* c, const uint32_t* a, uint32_t b0, uint32_t b1) {
    asm volatile(
        "mma.sync.aligned.m16n8k16.row.col.f32.bf16.bf16.f32 "
        "{%0,%1,%2,%3}, {%4,%5,%6,%7}, {%8,%9}, {%0,%1,%2,%3};\n"
        : "+f"(c[0]), "+f"(c[1]), "+f"(c[2]), "+f"(c[3])
        : "r"(a[0]), "r"(a[1]), "r"(a[2]), "r"(a[3]), "r"(b0), "r"(b1));
}
__device__ __forceinline__ void cpasync16(uint32_t dst, const void* src) {
    asm volatile("cp.async.cg.shared.global [%0], [%1], 16;\n" :: "r"(dst), "l"(src));
}
__device__ __forceinline__ void cp_commit() {
    asm volatile("cp.async.commit_group;\n" ::: "memory");
}
template <int N>
__device__ __forceinline__ void cp_wait() {
    asm volatile("cp.async.wait_group %0;\n" :: "n"(N) : "memory");
}

// stage one 128x128 bf16 weight slot into padded smem via cp.async (512 thr)
__device__ __forceinline__ void stage_w(int slot, __nv_bfloat16* Bs, int tid) {
    const __nv_bfloat16* wsrc = g_wcat + slot * (DDIM * CCH);
    #pragma unroll
    for (int i = 0; i < 4; i++) {
        int idx = tid + i * 512;                 // 0..2047 16B chunks
        int row = idx >> 4, sg = idx & 15;
        uint32_t dst = (uint32_t)__cvta_generic_to_shared(Bs + row * BPITCH + sg * 8);
        cpasync16(dst, wsrc + idx * 8);
    }
}

// ---------------------------------------------------------------------------
// Main fused kernel: one CTA = 2 sequences, 512 threads (16 warps).
// Warp (sq, wm, wn): sq = warp>>3, wm = (warp>>1)&3, wn = warp&1.
// Warp tile 32 (tokens) x 64 (channels): 64 fp32 acc regs (round-0 footprint).
// Each staged B slot serves BOTH sequences -> half the weight L2 traffic.
// ---------------------------------------------------------------------------
__global__ __launch_bounds__(512, 1)
void textcnn_kernel(const int* __restrict__ input_x,
                    const int* __restrict__ seg_ids,
                    const float* __restrict__ b3,
                    const float* __restrict__ b4,
                    const float* __restrict__ b5,
                    const float* __restrict__ Wout,
                    const float* __restrict__ bout,
                    float* __restrict__ out) {
    extern __shared__ char smem_raw[];
    __nv_bfloat16* Xs0  = (__nv_bfloat16*)smem_raw;              // XROWS * XPITCH
    __nv_bfloat16* Xs1  = Xs0 + XROWS * XPITCH;
    __nv_bfloat16* Bs0  = Xs1 + XROWS * XPITCH;                  // 128 * BPITCH
    __nv_bfloat16* Bs1  = Bs0 + 128 * BPITCH;
    float*         red  = (float*)(Bs1 + 128 * BPITCH);          // 8 * 128
    float*         feat = red + 8 * 128;                         // 2 * 384
    int*           ids  = (int*)(feat + 2 * 384);                // 256

    const int tid  = threadIdx.x;
    const int lane = tid & 31;
    const int warp = tid >> 5;
    const int sq   = warp >> 3;        // 0/1 : sequence
    const int wm   = (warp >> 1) & 3;  // 0..3 : M tile of 32 rows
    const int wn   = warp & 1;         // 0..1 : N tile of 64 cols
    __nv_bfloat16* Xw = sq ? Xs1 : Xs0;

    // ---- token ids for both sequences ----
    if (tid < 2 * SLEN) ids[tid] = input_x[blockIdx.x * (2 * SLEN) + tid];

    // ---- prefetch first two weight slots (async, overlaps gather) ----
    stage_w(0, Bs0, tid); cp_commit();
    stage_w(1, Bs1, tid); cp_commit();

    __syncthreads();   // ids visible

    // ---- gather embedding rows into padded smem (bf16) ----
    #pragma unroll
    for (int i = 0; i < 16; i++) {
        int r = warp * 16 + i;                      // 0..255
        __nv_bfloat16* X = (r < 128) ? Xs0 : Xs1;
        int rr = r & 127;
        const uint2* src = (const uint2*)(g_emb + (size_t)ids[r] * DDIM);
        *(uint2*)(X + rr * XPITCH + lane * 4) = src[lane];
    }
    // zero-pad rows 128..131 in both buffers
    const __nv_bfloat16 zb = __float2bfloat16(0.0f);
    for (int i = tid; i < 4 * XPITCH; i += 512) {
        Xs0[128 * XPITCH + i] = zb;
        Xs1[128 * XPITCH + i] = zb;
    }

    int slot = 0;
    #pragma unroll 1
    for (int conv = 0; conv < 3; conv++) {
        const int ksz = conv + 3;
        float acc[2][8][4];
        #pragma unroll
        for (int mf = 0; mf < 2; mf++)
            #pragma unroll
            for (int nf = 0; nf < 8; nf++)
                #pragma unroll
                for (int q = 0; q < 4; q++) acc[mf][nf][q] = 0.0f;

        #pragma unroll 1
        for (int j = 0; j < ksz; j++, slot++) {
            if (slot < NSLOT - 1) cp_wait<1>(); else cp_wait<0>();
            __syncthreads();                       // this slot's buffer full
            __nv_bfloat16* Bw = (slot & 1) ? Bs1 : Bs0;

            #pragma unroll 1
            for (int dc = 0; dc < 8; dc++) {
                // A fragments: rows shifted by j (implicit im2col)
                uint32_t a[2][4];
                #pragma unroll
                for (int mf = 0; mf < 2; mf++) {
                    int r = wm * 32 + mf * 16 + (lane & 15) + j;
                    int c = dc * 16 + (lane >> 4) * 8;
                    ldsm_x4(a[mf], (uint32_t)__cvta_generic_to_shared(Xw + r * XPITCH + c));
                }
                #pragma unroll
                for (int nc = 0; nc < 4; nc++) {
                    uint32_t b[4];
                    int br = dc * 16 + (lane & 15);
                    int bc = wn * 64 + nc * 16 + (lane >> 4) * 8;
                    ldsm_x4_t(b, (uint32_t)__cvta_generic_to_shared(Bw + br * BPITCH + bc));
                    #pragma unroll
                    for (int mf = 0; mf < 2; mf++) {
                        mma_bf16(acc[mf][nc * 2 + 0], a[mf], b[0], b[1]);
                        mma_bf16(acc[mf][nc * 2 + 1], a[mf], b[2], b[3]);
                    }
                }
            }
            __syncthreads();                       // all warps done reading Bw
            if (slot + 2 < NSLOT) { stage_w(slot + 2, Bw, tid); cp_commit(); }
        }

        // ---- maxpool over valid positions t <= SLEN - ksz ----
        const int tmax = SLEN - ksz;
        const float NEG = -1e30f;
        float lmax[8][2];
        #pragma unroll
        for (int nf = 0; nf < 8; nf++) {
            float m0 = NEG, m1 = NEG;
            #pragma unroll
            for (int mf = 0; mf < 2; mf++) {
                int r0 = wm * 32 + mf * 16 + (lane >> 2);
                bool v0 = (r0 <= tmax);
                bool v1 = (r0 + 8 <= tmax);
                m0 = fmaxf(m0, v0 ? acc[mf][nf][0] : NEG);
                m1 = fmaxf(m1, v0 ? acc[mf][nf][1] : NEG);
                m0 = fmaxf(m0, v1 ? acc[mf][nf][2] : NEG);
                m1 = fmaxf(m1, v1 ? acc[mf][nf][3] : NEG);
            }
            lmax[nf][0] = m0; lmax[nf][1] = m1;
        }
        #pragma unroll
        for (int nf = 0; nf < 8; nf++)
            #pragma unroll
            for (int p = 0; p < 2; p++) {
                float v = lmax[nf][p];
                v = fmaxf(v, __shfl_xor_sync(0xffffffffu, v, 4));
                v = fmaxf(v, __shfl_xor_sync(0xffffffffu, v, 8));
                v = fmaxf(v, __shfl_xor_sync(0xffffffffu, v, 16));
                lmax[nf][p] = v;
            }
        if ((lane >> 2) == 0) {
            #pragma unroll
            for (int nf = 0; nf < 8; nf++)
                #pragma unroll
                for (int p = 0; p < 2; p++)
                    red[(sq * 4 + wm) * 128 + wn * 64 + nf * 8 + (lane & 3) * 2 + p] = lmax[nf][p];
        }
        __syncthreads();
        if (tid < 2 * CCH) {
            int s = tid >> 7, c = tid & 127;
            float* rs = red + s * 4 * 128;
            float v = fmaxf(fmaxf(rs[c], rs[128 + c]),
                            fmaxf(rs[256 + c], rs[384 + c]));
            const float* bias = (conv == 0) ? b3 : ((conv == 1) ? b4 : b5);
            feat[s * 384 + conv * CCH + c] = v + bias[c];
        }
        __syncthreads();   // feat written; red free for reuse
    }

    // ---- output GEMM + sigmoid + segment max (2 seqs x 200 classes) ----
    if (tid < 2 * NCLS) {
        int s = (tid < NCLS) ? 0 : 1;
        int c = tid - s * NCLS;
        const float* f = feat + s * 384;
        float a = bout[c];
        #pragma unroll 4
        for (int kk = 0; kk < 3 * CCH; kk++)
            a = fmaf(f[kk], Wout[kk * NCLS + c], a);
        float sgm = 1.0f / (1.0f + expf(-a));
        int seg = seg_ids[blockIdx.x * 2 + s];
        atomicMax((int*)&out[seg * NCLS + c], __float_as_int(sgm));  // sgm > 0
    }
}

// ---------------------------------------------------------------------------
// Launch
// ---------------------------------------------------------------------------
extern "C" void kernel_launch(void* const* d_in, const int* in_sizes, int n_in,
                              void* d_out, int out_size) {
    const int*   input_x = (const int*)d_in[0];
    const int*   seg_ids = (const int*)d_in[1];
    const float* emb     = (const float*)d_in[2];
    const float* W3      = (const float*)d_in[3];
    const float* b3      = (const float*)d_in[4];
    const float* W4      = (const float*)d_in[5];
    const float* b4      = (const float*)d_in[6];
    const float* W5      = (const float*)d_in[7];
    const float* b5      = (const float*)d_in[8];
    const float* Wout    = (const float*)d_in[9];
    const float* bout    = (const float*)d_in[10];
    float*       out     = (float*)d_out;

    const int smem_bytes = (2 * XROWS * XPITCH + 2 * 128 * BPITCH) * 2  // Xs0/1 + Bs0/1
                         + (8 * 128 + 2 * 384) * 4                      // red + feat
                         + 256 * 4;                                     // ids
    cudaFuncSetAttribute(textcnn_kernel, cudaFuncAttributeMaxDynamicSharedMemorySize, smem_bytes);

    {
        int64_t nemb = (int64_t)VOCAB * DDIM;
        cvt_emb_kernel<<<(int)((nemb + 255) / 256), 256>>>(emb);
    }
    cvt_w_kernel<<<(NSLOT * DDIM * CCH + 255) / 256, 256>>>(W3, W4, W5);
    zero_out_kernel<<<(NVID * NCLS + 255) / 256, 256>>>(out);

    textcnn_kernel<<<NSEQ / 2, 512, smem_bytes>>>(input_x, seg_ids, b3, b4, b5, Wout, bout, out);
}

// round 6
// speedup vs baseline: 1.2597x; 1.2597x over previous
#include <cuda_runtime.h>
#include <cuda_bf16.h>
#include <cuda_fp8.h>
#include <cstdint>

// Problem constants
#define VOCAB   50000
#define DDIM    128
#define CCH     128
#define NCLS    200
#define NSEQ    4096
#define SLEN    128
#define NVID    256
#define NSLOT   12

// fp8 scaling: x*256, w*64 -> product scale 16384
#define XSCALE  256.0f
#define WSCALE  64.0f
#define INVS    (1.0f / 16384.0f)

// smem layout (bytes): X rows 132 x pitch 144 (fp8), 3 B buffers 128 x 144
#define XROWS   132
#define PITCH   144
#define X_BYTES (XROWS * PITCH)            // 19008
#define B_BYTES (128 * PITCH)              // 18432
#define OFF_X   0
#define OFF_B   (X_BYTES)                  // 3 buffers at OFF_B + i*B_BYTES
#define OFF_RED (OFF_B + 3 * B_BYTES)      // 4*128 floats
#define OFF_FEAT (OFF_RED + 2048)          // 384 floats
#define OFF_IDS (OFF_FEAT + 1536)          // 128 ints
#define SMEM_TOTAL (OFF_IDS + 512 + 32)

// Scratch in device globals (no allocations allowed)
__device__ uint8_t g_e8[(size_t)VOCAB * DDIM];            // fp8 e4m3, x*256
__device__ uint8_t g_w8[NSLOT * DDIM * CCH];              // fp8 e4m3, w*64, [slot][c][d]

// ---------------------------------------------------------------------------
// Conversion / init kernels
// ---------------------------------------------------------------------------
__global__ void cvt_emb8_kernel(const float* __restrict__ emb) {
    int64_t i = (int64_t)blockIdx.x * blockDim.x + threadIdx.x;
    int64_t n = (int64_t)VOCAB * DDIM;
    if (i < n)
        g_e8[i] = (uint8_t)__nv_cvt_float_to_fp8(emb[i] * XSCALE, __NV_SATFINITE, __NV_E4M3);
}

// W[slot][d][c] -> g_w8[slot][c][d]  (transpose so B rows are n-major, k-contig)
__global__ void cvt_w8_kernel(const float* __restrict__ W3,
                              const float* __restrict__ W4,
                              const float* __restrict__ W5) {
    int i = blockIdx.x * blockDim.x + threadIdx.x;          // < 196608
    if (i >= NSLOT * DDIM * CCH) return;
    int slot = i >> 14;                 // /16384
    int r    = i & 16383;
    int c    = r >> 7;                  // 0..127 (output channel)
    int d    = r & 127;                 // 0..127 (embedding dim = k)
    float v;
    if (slot < 3)      v = W3[(slot)     * 16384 + d * CCH + c];
    else if (slot < 7) v = W4[(slot - 3) * 16384 + d * CCH + c];
    else               v = W5[(slot - 7) * 16384 + d * CCH + c];
    g_w8[slot * 16384 + c * 128 + d] =
        (uint8_t)__nv_cvt_float_to_fp8(v * WSCALE, __NV_SATFINITE, __NV_E4M3);
}

__global__ void zero_out_kernel(float* __restrict__ out) {
    int i = blockIdx.x * blockDim.x + threadIdx.x;
    if (i < NVID * NCLS) out[i] = 0.0f;   // sigmoid scores are > 0, so 0 is a safe -inf
}

// ---------------------------------------------------------------------------
// MMA / async-copy helpers
// ---------------------------------------------------------------------------
__device__ __forceinline__ void ldsm_x4(uint32_t* r, uint32_t addr) {
    asm volatile("ldmatrix.sync.aligned.m8n8.x4.shared.b16 {%0,%1,%2,%3}, [%4];\n"
                 : "=r"(r[0]), "=r"(r[1]), "=r"(r[2]), "=r"(r[3]) : "r"(addr));
}
// fp8 e4m3 MMA, fp32 accumulate: D += A(16x32) * B(32x8)^T per n-octet
__device__ __forceinline__ void mma_fp8(float* c, const uint32_t* a, uint32_t b0, uint32_t b1) {
    asm volatile(
        "mma.sync.aligned.m16n8k32.row.col.f32.e4m3.e4m3.f32 "
        "{%0,%1,%2,%3}, {%4,%5,%6,%7}, {%8,%9}, {%0,%1,%2,%3};\n"
        : "+f"(c[0]), "+f"(c[1]), "+f"(c[2]), "+f"(c[3])
        : "r"(a[0]), "r"(a[1]), "r"(a[2]), "r"(a[3]), "r"(b0), "r"(b1));
}
__device__ __forceinline__ void cpasync16(uint32_t dst, const void* src) {
    asm volatile("cp.async.cg.shared.global [%0], [%1], 16;\n" :: "r"(dst), "l"(src));
}
__device__ __forceinline__ void cp_commit() {
    asm volatile("cp.async.commit_group;\n" ::: "memory");
}
template <int N>
__device__ __forceinline__ void cp_wait() {
    asm volatile("cp.async.wait_group %0;\n" :: "n"(N) : "memory");
}

// stage one weight slot [128 c][128 d bytes] into pitch-144 smem
__device__ __forceinline__ void stage_w(int slot, uint32_t bbase, int tid) {
    const uint8_t* src = g_w8 + slot * 16384;
    #pragma unroll
    for (int i = 0; i < 4; i++) {
        int idx = tid + i * 256;                 // 0..1023 16B chunks
        int row = idx >> 3, ch = idx & 7;
        cpasync16(bbase + row * PITCH + ch * 16, src + idx * 16);
    }
}

// ---------------------------------------------------------------------------
// Main fused kernel: one CTA per sequence, 8 warps, warp tile 32x64,
// fp8 e4m3 mma.m16n8k32, triple-buffered cp.async weight staging.
// ---------------------------------------------------------------------------
__global__ __launch_bounds__(256, 2)
void textcnn_kernel(const int* __restrict__ input_x,
                    const int* __restrict__ seg_ids,
                    const float* __restrict__ b3,
                    const float* __restrict__ b4,
                    const float* __restrict__ b5,
                    const float* __restrict__ Wout,
                    const float* __restrict__ bout,
                    float* __restrict__ out) {
    extern __shared__ char smem[];
    float* red  = (float*)(smem + OFF_RED);    // [4][128]
    float* feat = (float*)(smem + OFF_FEAT);   // [384]
    int*   ids  = (int*)(smem + OFF_IDS);      // [128]

    const int tid  = threadIdx.x;
    const int lane = tid & 31;
    const int warp = tid >> 5;
    const int wm   = warp >> 1;   // 0..3 : M tile of 32 rows
    const int wn   = warp & 1;    // 0..1 : N tile of 64 cols
    const int n    = blockIdx.x;

    const uint32_t sb = (uint32_t)__cvta_generic_to_shared(smem);
    const uint32_t xb = sb + OFF_X;

    // ---- token ids ----
    if (tid < SLEN) ids[tid] = input_x[n * SLEN + tid];
    __syncthreads();

    // ---- gather X (fp8 rows, 128B each) into pitch-144 smem : group g0 ----
    #pragma unroll
    for (int i = 0; i < 4; i++) {
        int idx = tid + i * 256;               // 0..1023
        int t = idx >> 3, ch = idx & 7;
        cpasync16(xb + t * PITCH + ch * 16, g_e8 + (size_t)ids[t] * DDIM + ch * 16);
    }
    cp_commit();
    // ---- prefetch weight slots 0,1 : groups g1,g2 ----
    stage_w(0, sb + OFF_B, tid);              cp_commit();
    stage_w(1, sb + OFF_B + B_BYTES, tid);    cp_commit();
    // zero-pad rows 128..131 (128B each)
    if (tid < 32) {
        int row = 128 + (tid >> 3), ch = tid & 7;
        *(uint4*)(smem + OFF_X + row * PITCH + ch * 16) = make_uint4(0, 0, 0, 0);
    }

    int slot = 0;
    #pragma unroll 1
    for (int conv = 0; conv < 3; conv++) {
        const int ksz = conv + 3;
        float acc[2][8][4];
        #pragma unroll
        for (int mf = 0; mf < 2; mf++)
            #pragma unroll
            for (int nf = 0; nf < 8; nf++)
                #pragma unroll
                for (int q = 0; q < 4; q++) acc[mf][nf][q] = 0.0f;

        #pragma unroll 1
        for (int j = 0; j < ksz; j++, slot++) {
            if (slot < NSLOT - 1) cp_wait<1>(); else cp_wait<0>();
            __syncthreads();                   // slot's buffer staged; slot-1 compute done
            // stage slot+2 into buffer (slot+2)%3 (was read by slot-1, now free)
            if (slot + 2 < NSLOT) {
                stage_w(slot + 2, sb + OFF_B + ((slot + 2) % 3) * B_BYTES, tid);
                cp_commit();
            }
            const uint32_t bw = sb + OFF_B + (slot % 3) * B_BYTES;

            #pragma unroll
            for (int dck = 0; dck < 4; dck++) {
                // A fragments m32 x k32 (rows shifted by j : implicit im2col)
                uint32_t a[2][4];
                #pragma unroll
                for (int mf = 0; mf < 2; mf++) {
                    int r = wm * 32 + mf * 16 + (lane & 15) + j;
                    ldsm_x4(a[mf], xb + r * PITCH + dck * 32 + (lane >> 4) * 16);
                }
                #pragma unroll
                for (int ng = 0; ng < 4; ng++) {
                    // B: two n-octets x k32 via one ldmatrix.x4
                    uint32_t b[4];
                    int brow = wn * 64 + ng * 16 + (lane & 7) + ((lane >> 4) << 3);
                    ldsm_x4(b, bw + brow * PITCH + dck * 32 + (((lane >> 3) & 1) << 4));
                    mma_fp8(acc[0][ng * 2 + 0], a[0], b[0], b[1]);
                    mma_fp8(acc[1][ng * 2 + 0], a[1], b[0], b[1]);
                    mma_fp8(acc[0][ng * 2 + 1], a[0], b[2], b[3]);
                    mma_fp8(acc[1][ng * 2 + 1], a[1], b[2], b[3]);
                }
            }
        }

        // ---- maxpool over valid positions t <= SLEN - ksz ----
        const int tmax = SLEN - ksz;
        const float NEG = -1e30f;
        float lmax[8][2];
        #pragma unroll
        for (int nf = 0; nf < 8; nf++) {
            float m0 = NEG, m1 = NEG;
            #pragma unroll
            for (int mf = 0; mf < 2; mf++) {
                int r0 = wm * 32 + mf * 16 + (lane >> 2);
                bool v0 = (r0 <= tmax);
                bool v1 = (r0 + 8 <= tmax);
                m0 = fmaxf(m0, v0 ? acc[mf][nf][0] : NEG);
                m1 = fmaxf(m1, v0 ? acc[mf][nf][1] : NEG);
                m0 = fmaxf(m0, v1 ? acc[mf][nf][2] : NEG);
                m1 = fmaxf(m1, v1 ? acc[mf][nf][3] : NEG);
            }
            lmax[nf][0] = m0; lmax[nf][1] = m1;
        }
        #pragma unroll
        for (int nf = 0; nf < 8; nf++)
            #pragma unroll
            for (int p = 0; p < 2; p++) {
                float v = lmax[nf][p];
                v = fmaxf(v, __shfl_xor_sync(0xffffffffu, v, 4));
                v = fmaxf(v, __shfl_xor_sync(0xffffffffu, v, 8));
                v = fmaxf(v, __shfl_xor_sync(0xffffffffu, v, 16));
                lmax[nf][p] = v;
            }
        if ((lane >> 2) == 0) {
            #pragma unroll
            for (int nf = 0; nf < 8; nf++)
                #pragma unroll
                for (int p = 0; p < 2; p++)
                    red[wm * 128 + wn * 64 + nf * 8 + (lane & 3) * 2 + p] = lmax[nf][p];
        }
        __syncthreads();
        if (tid < CCH) {
            float v = fmaxf(fmaxf(red[tid], red[128 + tid]),
                            fmaxf(red[256 + tid], red[384 + tid]));
            const float* bias = (conv == 0) ? b3 : ((conv == 1) ? b4 : b5);
            feat[conv * CCH + tid] = v * INVS + bias[tid];     // descale fp8 product
        }
        __syncthreads();   // feat written; red free for reuse
    }

    // ---- output GEMM + sigmoid + segment max (fp32) ----
    if (tid < NCLS) {
        float a = bout[tid];
        #pragma unroll 4
        for (int kk = 0; kk < 3 * CCH; kk++)
            a = fmaf(feat[kk], Wout[kk * NCLS + tid], a);
        float s = 1.0f / (1.0f + expf(-a));
        int seg = seg_ids[n];
        atomicMax((int*)&out[seg * NCLS + tid], __float_as_int(s));  // s > 0
    }
}

// ---------------------------------------------------------------------------
// Launch
// ---------------------------------------------------------------------------
extern "C" void kernel_launch(void* const* d_in, const int* in_sizes, int n_in,
                              void* d_out, int out_size) {
    const int*   input_x = (const int*)d_in[0];
    const int*   seg_ids = (const int*)d_in[1];
    const float* emb     = (const float*)d_in[2];
    const float* W3      = (const float*)d_in[3];
    const float* b3      = (const float*)d_in[4];
    const float* W4      = (const float*)d_in[5];
    const float* b4      = (const float*)d_in[6];
    const float* W5      = (const float*)d_in[7];
    const float* b5      = (const float*)d_in[8];
    const float* Wout    = (const float*)d_in[9];
    const float* bout    = (const float*)d_in[10];
    float*       out     = (float*)d_out;

    cudaFuncSetAttribute(textcnn_kernel, cudaFuncAttributeMaxDynamicSharedMemorySize, SMEM_TOTAL);

    {
        int64_t nemb = (int64_t)VOCAB * DDIM;
        cvt_emb8_kernel<<<(int)((nemb + 255) / 256), 256>>>(emb);
    }
    cvt_w8_kernel<<<(NSLOT * DDIM * CCH + 255) / 256, 256>>>(W3, W4, W5);
    zero_out_kernel<<<(NVID * NCLS + 255) / 256, 256>>>(out);

    textcnn_kernel<<<NSEQ, 256, SMEM_TOTAL>>>(input_x, seg_ids, b3, b4, b5, Wout, bout, out);
}